// round 8
// baseline (speedup 1.0000x reference)
#include <cuda_runtime.h>
#include <cstddef>

// Problem dims (fixed): (B=2, C=1, D=160, H=192, W=160) fp32, WIN=9 box, zero pad
#define Bn 2
#define Dn 160
#define Hn 192
#define Wn 160
#define Rr 4
#define HW (Hn*Wn)
#define DHW (Dn*HW)
#define NB (Bn*DHW)          // 9,830,400
#define NCH 5
#define NQ (Wn/4)            // 40 w-quads

// K1 (H-filter) decomposition
#define HSPLIT 4
#define HCHUNK (Hn/HSPLIT)   // 48
#define HSUB (HCHUNK/4)      // 12 output rows per thread

// K2 (D-filter + W-filter + cc): scalar thread per w, one h-row per block
#define DSPLIT 4
#define DCHUNK (Dn/DSPLIT)   // 40
#define NPART (Bn*Hn*DSPLIT) // 1536

#define SROWP (Wn + 2*Rr)    // 168 padded row

// Scratch layout TRANSPOSED: [ch][b][h][d][w]  (d-stride = 640 B)
__device__ float g_buf[NCH * NB];
__device__ double g_part[NPART];
__device__ unsigned int g_done = 0;

__device__ __forceinline__ float4 f4zero() { return make_float4(0.f,0.f,0.f,0.f); }
#define ADD4(S,V) do{ S.x+=V.x; S.y+=V.y; S.z+=V.z; S.w+=V.w; }while(0)
#define SUB4(S,V) do{ S.x-=V.x; S.y-=V.y; S.z-=V.z; S.w-=V.w; }while(0)

// ---------------------------------------------------------------------------
// K1: 9-tap H-filter on raw voxels, 5 stat channels. Rolling window along h;
// subtract side reloads the raw row (small stride -> cache hit, exact
// telescoping). Writes TRANSPOSED scratch [ch][b][h][d][w].
// Thread = one w-quad, one 12-row h substream. No smem, no syncs.
// ---------------------------------------------------------------------------
__global__ void __launch_bounds__(160)
pass_h(const float* __restrict__ I, const float* __restrict__ J,
       float* __restrict__ out) {
    const int blk = blockIdx.x;
    const int hs  = blk % HSPLIT;
    const int rem = blk / HSPLIT;
    const int d   = rem % Dn;
    const int b   = rem / Dn;

    const int tid  = threadIdx.x;
    const int wq   = tid % NQ;
    const int hsub = tid / NQ;                 // 0..3
    const int hbeg = hs * HCHUNK + hsub * HSUB;

    const size_t pbase = (size_t)b * DHW + (size_t)d * HW + 4*wq;
    const float* bI = I + pbase;
    const float* bJ = J + pbase;
    float* bO = out + (size_t)b * DHW + (size_t)d * Wn + 4*wq;

    float4 S0=f4zero(), S1=f4zero(), S2=f4zero(), S3=f4zero(), S4=f4zero();

    for (int r = hbeg - Rr; r <= hbeg + HSUB + Rr - 1; ++r) {
        if ((unsigned)r < (unsigned)Hn) {
            const float4 a = *(const float4*)(bI + (size_t)r * Wn);
            const float4 q = *(const float4*)(bJ + (size_t)r * Wn);
            ADD4(S0,a); ADD4(S1,q);
            S2.x += a.x*a.x; S2.y += a.y*a.y; S2.z += a.z*a.z; S2.w += a.w*a.w;
            S3.x += q.x*q.x; S3.y += q.y*q.y; S3.z += q.z*q.z; S3.w += q.w*q.w;
            S4.x += a.x*q.x; S4.y += a.y*q.y; S4.z += a.z*q.z; S4.w += a.w*q.w;
        }
        const int o = r - Rr;
        if (o >= hbeg) {
            float* op = bO + (size_t)o * (Dn * Wn);
            *(float4*)(op + 0*(size_t)NB) = S0;
            *(float4*)(op + 1*(size_t)NB) = S1;
            *(float4*)(op + 2*(size_t)NB) = S2;
            *(float4*)(op + 3*(size_t)NB) = S3;
            *(float4*)(op + 4*(size_t)NB) = S4;

            const int qr = o - Rr;             // row leaving the window
            if (qr >= 0) {
                const float4 a = *(const float4*)(bI + (size_t)qr * Wn);
                const float4 q = *(const float4*)(bJ + (size_t)qr * Wn);
                SUB4(S0,a); SUB4(S1,q);
                S2.x -= a.x*a.x; S2.y -= a.y*a.y; S2.z -= a.z*a.z; S2.w -= a.w*a.w;
                S3.x -= q.x*q.x; S3.y -= q.y*q.y; S3.z -= q.z*q.z; S3.w -= q.w*q.w;
                S4.x -= a.x*q.x; S4.y -= a.y*q.y; S4.z -= a.z*q.z; S4.w -= a.w*q.w;
            }
        }
    }
}

// ---------------------------------------------------------------------------
// K2: D-filter (scalar register rolling window; add streams 640B-stride,
// subtract reloads are L2-resident: reuse window = 9/49 of kernel traffic),
// then W 9-tap via a double-buffered padded smem row (one sync per plane),
// then cc + global mean. Block: 160 threads = one (b,h) row. Grid:
// Bn*Hn*DSPLIT = 1536 (round-4 occupancy shape, ~35 regs).
// ---------------------------------------------------------------------------
__global__ void __launch_bounds__(160)
pass_d_w_cc(const float* __restrict__ in, float* __restrict__ outscalar) {
    __shared__ float sbuf[2][NCH][SROWP];

    const int blk   = blockIdx.x;
    const int chunk = blk % DSPLIT;
    const int id    = blk / DSPLIT;
    const int h     = id % Hn;
    const int b     = id / Hn;
    const int w     = threadIdx.x;

    // transposed: plane d of row h lives at ((h*Dn + d)*Wn)
    const float* __restrict__ p =
        in + (size_t)b * DHW + (size_t)h * (Dn * Wn) + w;

    const int o0 = chunk * DCHUNK;
    const int o1 = o0 + DCHUNK;

    // zero the W pads (both buffers): 2 buf x 5 ch x 8 pad = 80 entries
    for (int i = w; i < 80; i += 160) {
        const int bf = i / 40;
        const int ch = (i % 40) / 8;
        const int k  = i % 8;
        sbuf[bf][ch][(k < Rr) ? k : (Wn + k)] = 0.f;
    }

    // init D window: planes [max(0,o0-4) .. o0+4]  (o0+4 <= 124 < Dn always)
    float s0=0.f, s1=0.f, s2=0.f, s3=0.f, s4=0.f;
#pragma unroll
    for (int d = o0 - Rr; d <= o0 + Rr; ++d) {
        if (d >= 0) {
            const size_t off = (size_t)d * Wn;
            s0 += p[0*(size_t)NB + off];
            s1 += p[1*(size_t)NB + off];
            s2 += p[2*(size_t)NB + off];
            s3 += p[3*(size_t)NB + off];
            s4 += p[4*(size_t)NB + off];
        }
    }

    const float inv = 1.0f / 729.0f;
    float accf = 0.f;

    for (int o = o0; o < o1; ++o) {
        const int buf = o & 1;
        sbuf[buf][0][Rr + w] = s0;
        sbuf[buf][1][Rr + w] = s1;
        sbuf[buf][2][Rr + w] = s2;
        sbuf[buf][3][Rr + w] = s3;
        sbuf[buf][4][Rr + w] = s4;
        __syncthreads();

        // W 9-tap from smem (padded zeros at edges), then cc
        float W0=0.f, W1=0.f, W2=0.f, W3=0.f, W4=0.f;
#pragma unroll
        for (int k = 0; k < 9; ++k) {
            W0 += sbuf[buf][0][w + k];
            W1 += sbuf[buf][1][w + k];
            W2 += sbuf[buf][2][w + k];
            W3 += sbuf[buf][3][w + k];
            W4 += sbuf[buf][4][w + k];
        }
        {
            const float mu1 = W0 * inv, mu2 = W1 * inv;
            const float v1  = W2 * inv - mu1 * mu1;
            const float v2  = W3 * inv - mu2 * mu2;
            const float cv  = W4 * inv - mu1 * mu2;
            accf += __fdividef(cv * cv, v1 * v2 + 1e-5f);
        }

        // advance D window (add: streaming; sub: L2-resident reload)
        const int da = o + Rr + 1;
        const int ds = o - Rr;
        if (da < Dn) {
            const size_t off = (size_t)da * Wn;
            s0 += p[0*(size_t)NB + off];
            s1 += p[1*(size_t)NB + off];
            s2 += p[2*(size_t)NB + off];
            s3 += p[3*(size_t)NB + off];
            s4 += p[4*(size_t)NB + off];
        }
        if (ds >= 0) {
            const size_t off = (size_t)ds * Wn;
            s0 -= p[0*(size_t)NB + off];
            s1 -= p[1*(size_t)NB + off];
            s2 -= p[2*(size_t)NB + off];
            s3 -= p[3*(size_t)NB + off];
            s4 -= p[4*(size_t)NB + off];
        }
        // double-buffered: one sync per plane suffices (overwrite of buffer
        // o happens at stage(o+2), which is ordered after sync(o+1) which is
        // ordered after every thread's read(o)).
    }

    // Deterministic block reduction (160 -> 1)
    __shared__ double red[160];
    red[w] = (double)accf;
    __syncthreads();
    if (w < 32) red[w] += red[w + 128];
    __syncthreads();
#pragma unroll
    for (int s = 64; s > 0; s >>= 1) {
        if (w < s) red[w] += red[w + s];
        __syncthreads();
    }

    __shared__ int isLast;
    if (w == 0) {
        g_part[blk] = red[0];
        __threadfence();
        const unsigned v = atomicAdd(&g_done, 1u);
        isLast = (v == (unsigned)(gridDim.x - 1));
    }
    __syncthreads();

    if (isLast) {
        __threadfence();
        double a = 0.0;
        for (int i = w; i < NPART; i += 160) a += g_part[i];  // fixed order
        red[w] = a;
        __syncthreads();
        if (w < 32) red[w] += red[w + 128];
        __syncthreads();
#pragma unroll
        for (int s = 64; s > 0; s >>= 1) {
            if (w < s) red[w] += red[w + s];
            __syncthreads();
        }
        if (w == 0) {
            outscalar[0] = (float)(-red[0] / (double)NB);
            g_done = 0;   // reset for next graph replay
        }
    }
}

extern "C" void kernel_launch(void* const* d_in, const int* in_sizes, int n_in,
                              void* d_out, int out_size) {
    const float* I = (const float*)d_in[0];   // y_true
    const float* J = (const float*)d_in[1];   // y_pred
    float* out = (float*)d_out;

    float* buf;
    cudaGetSymbolAddress((void**)&buf, g_buf);

    pass_h<<<Bn * Dn * HSPLIT, 160>>>(I, J, buf);
    pass_d_w_cc<<<Bn * Hn * DSPLIT, 160>>>(buf, out);
}

// round 9
// speedup vs baseline: 1.0793x; 1.0793x over previous
#include <cuda_runtime.h>
#include <cstddef>

// Problem dims (fixed): (B=2, C=1, D=160, H=192, W=160) fp32, WIN=9 box, zero pad
#define Bn 2
#define Dn 160
#define Hn 192
#define Wn 160
#define Rr 4
#define HW (Hn*Wn)
#define DHW (Dn*HW)
#define NB (Bn*DHW)          // 9,830,400
#define NCH 5
#define NQ (Wn/4)            // 40 w-quads

// K1 (H-filter) decomposition
#define HSPLIT 4
#define HCHUNK (Hn/HSPLIT)   // 48
#define HSUB (HCHUNK/4)      // 12 output rows per thread

// K2 (D-filter + W-filter + cc): quad thread, 4 h-rows/block, DSPLIT=4
#define DSPLIT 4
#define DCHUNK (Dn/DSPLIT)   // 40
#define NROWS 4
#define NPART (Bn*(Hn/NROWS)*DSPLIT)   // 384

#define SROW 42              // padded quad row: [0]=left pad, [41]=right pad

// Scratch layout TRANSPOSED: [ch][b][h][d][w]  (d-stride = 640 B)
__device__ float g_buf[NCH * NB];
__device__ double g_part[NPART];
__device__ unsigned int g_done = 0;

__device__ __forceinline__ float4 f4zero() { return make_float4(0.f,0.f,0.f,0.f); }
#define ADD4(S,V) do{ S.x+=V.x; S.y+=V.y; S.z+=V.z; S.w+=V.w; }while(0)
#define SUB4(S,V) do{ S.x-=V.x; S.y-=V.y; S.z-=V.z; S.w-=V.w; }while(0)

// 12 consecutive values -> four 9-tap sliding sums
__device__ __forceinline__ float4 slide9(const float v[12]) {
    float s = v[0]+v[1]+v[2]+v[3]+v[4]+v[5]+v[6]+v[7]+v[8];
    float4 o;
    o.x = s; s += v[9]  - v[0];
    o.y = s; s += v[10] - v[1];
    o.z = s; s += v[11] - v[2];
    o.w = s;
    return o;
}

// ---------------------------------------------------------------------------
// K1: 9-tap H-filter on raw voxels, 5 stat channels. Rolling window along h;
// subtract side reloads the raw row (cache hit, exact telescoping).
// Writes TRANSPOSED scratch [ch][b][h][d][w]. No smem, no syncs.
// ---------------------------------------------------------------------------
__global__ void __launch_bounds__(160)
pass_h(const float* __restrict__ I, const float* __restrict__ J,
       float* __restrict__ out) {
    const int blk = blockIdx.x;
    const int hs  = blk % HSPLIT;
    const int rem = blk / HSPLIT;
    const int d   = rem % Dn;
    const int b   = rem / Dn;

    const int tid  = threadIdx.x;
    const int wq   = tid % NQ;
    const int hsub = tid / NQ;                 // 0..3
    const int hbeg = hs * HCHUNK + hsub * HSUB;

    const size_t pbase = (size_t)b * DHW + (size_t)d * HW + 4*wq;
    const float* bI = I + pbase;
    const float* bJ = J + pbase;
    float* bO = out + (size_t)b * DHW + (size_t)d * Wn + 4*wq;

    float4 S0=f4zero(), S1=f4zero(), S2=f4zero(), S3=f4zero(), S4=f4zero();

    for (int r = hbeg - Rr; r <= hbeg + HSUB + Rr - 1; ++r) {
        if ((unsigned)r < (unsigned)Hn) {
            const float4 a = *(const float4*)(bI + (size_t)r * Wn);
            const float4 q = *(const float4*)(bJ + (size_t)r * Wn);
            ADD4(S0,a); ADD4(S1,q);
            S2.x += a.x*a.x; S2.y += a.y*a.y; S2.z += a.z*a.z; S2.w += a.w*a.w;
            S3.x += q.x*q.x; S3.y += q.y*q.y; S3.z += q.z*q.z; S3.w += q.w*q.w;
            S4.x += a.x*q.x; S4.y += a.y*q.y; S4.z += a.z*q.z; S4.w += a.w*q.w;
        }
        const int o = r - Rr;
        if (o >= hbeg) {
            float* op = bO + (size_t)o * (Dn * Wn);
            *(float4*)(op + 0*(size_t)NB) = S0;
            *(float4*)(op + 1*(size_t)NB) = S1;
            *(float4*)(op + 2*(size_t)NB) = S2;
            *(float4*)(op + 3*(size_t)NB) = S3;
            *(float4*)(op + 4*(size_t)NB) = S4;

            const int qr = o - Rr;             // row leaving the window
            if (qr >= 0) {
                const float4 a = *(const float4*)(bI + (size_t)qr * Wn);
                const float4 q = *(const float4*)(bJ + (size_t)qr * Wn);
                SUB4(S0,a); SUB4(S1,q);
                S2.x -= a.x*a.x; S2.y -= a.y*a.y; S2.z -= a.z*a.z; S2.w -= a.w*a.w;
                S3.x -= q.x*q.x; S3.y -= q.y*q.y; S3.z -= q.z*q.z; S3.w -= q.w*q.w;
                S4.x -= a.x*q.x; S4.y -= a.y*q.y; S4.z -= a.z*q.z; S4.w -= a.w*q.w;
            }
        }
    }
}

// ---------------------------------------------------------------------------
// K2: D-filter (float4 register rolling window on transposed H-sums; add
// streams 640B-stride, subtract reloads are L2-resident at DSPLIT=4), then
// W 9-tap via double-buffered float4 smem rows (15 LDS.128 per 4 outputs),
// then cc + global mean. Block: 160 threads = 40 quads x 4 h-rows.
// Grid: Bn*(Hn/4)*DSPLIT = 384 (single wave).
// ---------------------------------------------------------------------------
__global__ void __launch_bounds__(160)
pass_d_w_cc(const float* __restrict__ in, float* __restrict__ outscalar) {
    __shared__ float4 sbuf[2][NROWS][NCH][SROW];

    const int blk   = blockIdx.x;
    const int chunk = blk % DSPLIT;
    const int id    = blk / DSPLIT;
    const int hg    = id % (Hn/NROWS);
    const int b     = id / (Hn/NROWS);

    const int tid  = threadIdx.x;
    const int wq   = tid % NQ;
    const int row4 = tid / NQ;                 // 0..3
    const int h    = hg * NROWS + row4;

    // transposed: plane d of row h lives at ((h*Dn + d)*Wn)
    const float* __restrict__ p =
        in + (size_t)b * DHW + (size_t)h * (Dn * Wn) + 4*wq;

    const int o0 = chunk * DCHUNK;
    const int o1 = o0 + DCHUNK;

    // zero the W pads once (both buffers): 2*4*5*2 = 80 float4s
    for (int i = tid; i < 80; i += 160) {
        const int side = i & 1;
        const int ch   = (i >> 1) % NCH;
        const int rr   = ((i >> 1) / NCH) % NROWS;
        const int bf   = (i >> 1) / (NCH * NROWS);
        sbuf[bf][rr][ch][side ? (SROW-1) : 0] = f4zero();
    }

    // init D window: planes [max(0,o0-4) .. o0+4]
    float4 S0=f4zero(), S1=f4zero(), S2=f4zero(), S3=f4zero(), S4=f4zero();
#pragma unroll
    for (int d = o0 - Rr; d <= o0 + Rr; ++d) {
        if (d >= 0) {
            const size_t off = (size_t)d * Wn;
            float4 v;
            v = *(const float4*)(p + 0*(size_t)NB + off); ADD4(S0,v);
            v = *(const float4*)(p + 1*(size_t)NB + off); ADD4(S1,v);
            v = *(const float4*)(p + 2*(size_t)NB + off); ADD4(S2,v);
            v = *(const float4*)(p + 3*(size_t)NB + off); ADD4(S3,v);
            v = *(const float4*)(p + 4*(size_t)NB + off); ADD4(S4,v);
        }
    }

    const float inv = 1.0f / 729.0f;
    float accf = 0.f;

    for (int o = o0; o < o1; ++o) {
        const int buf = o & 1;
        sbuf[buf][row4][0][1+wq] = S0;
        sbuf[buf][row4][1][1+wq] = S1;
        sbuf[buf][row4][2][1+wq] = S2;
        sbuf[buf][row4][3][1+wq] = S3;
        sbuf[buf][row4][4][1+wq] = S4;
        __syncthreads();

        // W 9-tap from smem (pads give zero boundary), then cc
        float4 W[NCH];
#pragma unroll
        for (int ch = 0; ch < NCH; ++ch) {
            const float4 L = sbuf[buf][row4][ch][wq];
            const float4 C = sbuf[buf][row4][ch][1+wq];
            const float4 R = sbuf[buf][row4][ch][2+wq];
            const float v[12] = {L.x,L.y,L.z,L.w, C.x,C.y,C.z,C.w, R.x,R.y,R.z,R.w};
            W[ch] = slide9(v);
        }
        {
            const float mu1=W[0].x*inv, mu2=W[1].x*inv;
            const float v1=W[2].x*inv-mu1*mu1, v2=W[3].x*inv-mu2*mu2, cv=W[4].x*inv-mu1*mu2;
            accf += __fdividef(cv*cv, v1*v2 + 1e-5f);
        }
        {
            const float mu1=W[0].y*inv, mu2=W[1].y*inv;
            const float v1=W[2].y*inv-mu1*mu1, v2=W[3].y*inv-mu2*mu2, cv=W[4].y*inv-mu1*mu2;
            accf += __fdividef(cv*cv, v1*v2 + 1e-5f);
        }
        {
            const float mu1=W[0].z*inv, mu2=W[1].z*inv;
            const float v1=W[2].z*inv-mu1*mu1, v2=W[3].z*inv-mu2*mu2, cv=W[4].z*inv-mu1*mu2;
            accf += __fdividef(cv*cv, v1*v2 + 1e-5f);
        }
        {
            const float mu1=W[0].w*inv, mu2=W[1].w*inv;
            const float v1=W[2].w*inv-mu1*mu1, v2=W[3].w*inv-mu2*mu2, cv=W[4].w*inv-mu1*mu2;
            accf += __fdividef(cv*cv, v1*v2 + 1e-5f);
        }

        // advance D window (add: streaming 640B stride; sub: L2-resident)
        const int da = o + Rr + 1;
        const int ds = o - Rr;
        if (da < Dn) {
            const size_t off = (size_t)da * Wn;
            float4 v;
            v = *(const float4*)(p + 0*(size_t)NB + off); ADD4(S0,v);
            v = *(const float4*)(p + 1*(size_t)NB + off); ADD4(S1,v);
            v = *(const float4*)(p + 2*(size_t)NB + off); ADD4(S2,v);
            v = *(const float4*)(p + 3*(size_t)NB + off); ADD4(S3,v);
            v = *(const float4*)(p + 4*(size_t)NB + off); ADD4(S4,v);
        }
        if (ds >= 0) {
            const size_t off = (size_t)ds * Wn;
            float4 v;
            v = *(const float4*)(p + 0*(size_t)NB + off); SUB4(S0,v);
            v = *(const float4*)(p + 1*(size_t)NB + off); SUB4(S1,v);
            v = *(const float4*)(p + 2*(size_t)NB + off); SUB4(S2,v);
            v = *(const float4*)(p + 3*(size_t)NB + off); SUB4(S3,v);
            v = *(const float4*)(p + 4*(size_t)NB + off); SUB4(S4,v);
        }
        // double-buffered: one sync per plane suffices
    }

    // Deterministic block reduction (160 -> 1)
    __shared__ double red[160];
    const int w = tid;
    red[w] = (double)accf;
    __syncthreads();
    if (w < 32) red[w] += red[w + 128];
    __syncthreads();
#pragma unroll
    for (int s = 64; s > 0; s >>= 1) {
        if (w < s) red[w] += red[w + s];
        __syncthreads();
    }

    __shared__ int isLast;
    if (w == 0) {
        g_part[blk] = red[0];
        __threadfence();
        const unsigned v = atomicAdd(&g_done, 1u);
        isLast = (v == (unsigned)(gridDim.x - 1));
    }
    __syncthreads();

    if (isLast) {
        __threadfence();
        double a = 0.0;
        for (int i = w; i < NPART; i += 160) a += g_part[i];  // fixed order
        red[w] = a;
        __syncthreads();
        if (w < 32) red[w] += red[w + 128];
        __syncthreads();
#pragma unroll
        for (int s = 64; s > 0; s >>= 1) {
            if (w < s) red[w] += red[w + s];
            __syncthreads();
        }
        if (w == 0) {
            outscalar[0] = (float)(-red[0] / (double)NB);
            g_done = 0;   // reset for next graph replay
        }
    }
}

extern "C" void kernel_launch(void* const* d_in, const int* in_sizes, int n_in,
                              void* d_out, int out_size) {
    const float* I = (const float*)d_in[0];   // y_true
    const float* J = (const float*)d_in[1];   // y_pred
    float* out = (float*)d_out;

    float* buf;
    cudaGetSymbolAddress((void**)&buf, g_buf);

    pass_h<<<Bn * Dn * HSPLIT, 160>>>(I, J, buf);
    pass_d_w_cc<<<Bn * (Hn/NROWS) * DSPLIT, 160>>>(buf, out);
}

// round 10
// speedup vs baseline: 1.5227x; 1.4109x over previous
#include <cuda_runtime.h>
#include <cuda_fp16.h>
#include <cstddef>

// Problem dims (fixed): (B=2, C=1, D=160, H=192, W=160) fp32, WIN=9 box, zero pad
#define Bn 2
#define Dn 160
#define Hn 192
#define Wn 160
#define Rr 4
#define HW (Hn*Wn)
#define DHW (Dn*HW)
#define NB (Bn*DHW)          // 9,830,400
#define NCH 5
#define NQ (Wn/4)            // 40 w-quads

// K1 (H-filter) decomposition
#define HSPLIT 4
#define HCHUNK (Hn/HSPLIT)   // 48
#define HSUB (HCHUNK/4)      // 12 output rows per thread

// K2 (D-filter + W-filter + cc): quad thread, 4 h-rows/block, DSPLIT=8
// fp16 scratch halves the L2 reuse footprint -> DSPLIT=8 stays resident.
#define DSPLIT 8
#define DCHUNK (Dn/DSPLIT)   // 20
#define NROWS 4
#define NPART (Bn*(Hn/NROWS)*DSPLIT)   // 768

#define SROW 42              // padded quad row: [0]=left pad, [41]=right pad

// Scratch TRANSPOSED fp16: [ch][b][h][d][w]  (d-stride = 320 B)
// Declared as uint2 for guaranteed 8B alignment of quad accesses.
__device__ uint2 g_buf[(size_t)NCH * NB / 4];   // ~98.3 MB
__device__ double g_part[NPART];
__device__ unsigned int g_done = 0;

__device__ __forceinline__ float4 f4zero() { return make_float4(0.f,0.f,0.f,0.f); }
#define ADD4(S,V) do{ S.x+=V.x; S.y+=V.y; S.z+=V.z; S.w+=V.w; }while(0)
#define SUB4(S,V) do{ S.x-=V.x; S.y-=V.y; S.z-=V.z; S.w-=V.w; }while(0)

// one 8B load -> 4 floats
__device__ __forceinline__ float4 ldh4(const __half* a) {
    const uint2 u = *(const uint2*)a;
    const __half2 h0 = *(const __half2*)&u.x;
    const __half2 h1 = *(const __half2*)&u.y;
    const float2 lo = __half22float2(h0);
    const float2 hi = __half22float2(h1);
    return make_float4(lo.x, lo.y, hi.x, hi.y);
}
// 4 floats -> one 8B store (round-to-nearest)
__device__ __forceinline__ void sth4(__half* a, float4 v) {
    const __half2 h0 = __floats2half2_rn(v.x, v.y);
    const __half2 h1 = __floats2half2_rn(v.z, v.w);
    uint2 u;
    u.x = *(const unsigned*)&h0;
    u.y = *(const unsigned*)&h1;
    *(uint2*)a = u;
}

// 12 consecutive values -> four 9-tap sliding sums
__device__ __forceinline__ float4 slide9(const float v[12]) {
    float s = v[0]+v[1]+v[2]+v[3]+v[4]+v[5]+v[6]+v[7]+v[8];
    float4 o;
    o.x = s; s += v[9]  - v[0];
    o.y = s; s += v[10] - v[1];
    o.z = s; s += v[11] - v[2];
    o.w = s;
    return o;
}

// ---------------------------------------------------------------------------
// K1: 9-tap H-filter on raw voxels, 5 stat channels, fp32 accumulate.
// Rolling window along h; subtract side reloads the raw row (L1 hit, exact
// telescoping). Writes TRANSPOSED fp16 scratch [ch][b][h][d][w].
// Thread = one w-quad, one 12-row h substream. No smem, no syncs.
// ---------------------------------------------------------------------------
__global__ void __launch_bounds__(160)
pass_h(const float* __restrict__ I, const float* __restrict__ J,
       __half* __restrict__ out) {
    const int blk = blockIdx.x;
    const int hs  = blk % HSPLIT;
    const int rem = blk / HSPLIT;
    const int d   = rem % Dn;
    const int b   = rem / Dn;

    const int tid  = threadIdx.x;
    const int wq   = tid % NQ;
    const int hsub = tid / NQ;                 // 0..3
    const int hbeg = hs * HCHUNK + hsub * HSUB;

    const size_t pbase = (size_t)b * DHW + (size_t)d * HW + 4*wq;
    const float* bI = I + pbase;
    const float* bJ = J + pbase;
    __half* bO = out + (size_t)b * DHW + (size_t)d * Wn + 4*wq;

    float4 S0=f4zero(), S1=f4zero(), S2=f4zero(), S3=f4zero(), S4=f4zero();

    for (int r = hbeg - Rr; r <= hbeg + HSUB + Rr - 1; ++r) {
        if ((unsigned)r < (unsigned)Hn) {
            const float4 a = *(const float4*)(bI + (size_t)r * Wn);
            const float4 q = *(const float4*)(bJ + (size_t)r * Wn);
            ADD4(S0,a); ADD4(S1,q);
            S2.x += a.x*a.x; S2.y += a.y*a.y; S2.z += a.z*a.z; S2.w += a.w*a.w;
            S3.x += q.x*q.x; S3.y += q.y*q.y; S3.z += q.z*q.z; S3.w += q.w*q.w;
            S4.x += a.x*q.x; S4.y += a.y*q.y; S4.z += a.z*q.z; S4.w += a.w*q.w;
        }
        const int o = r - Rr;
        if (o >= hbeg) {
            __half* op = bO + (size_t)o * (Dn * Wn);
            sth4(op + 0*(size_t)NB, S0);
            sth4(op + 1*(size_t)NB, S1);
            sth4(op + 2*(size_t)NB, S2);
            sth4(op + 3*(size_t)NB, S3);
            sth4(op + 4*(size_t)NB, S4);

            const int qr = o - Rr;             // row leaving the window
            if (qr >= 0) {
                const float4 a = *(const float4*)(bI + (size_t)qr * Wn);
                const float4 q = *(const float4*)(bJ + (size_t)qr * Wn);
                SUB4(S0,a); SUB4(S1,q);
                S2.x -= a.x*a.x; S2.y -= a.y*a.y; S2.z -= a.z*a.z; S2.w -= a.w*a.w;
                S3.x -= q.x*q.x; S3.y -= q.y*q.y; S3.z -= q.z*q.z; S3.w -= q.w*q.w;
                S4.x -= a.x*q.x; S4.y -= a.y*q.y; S4.z -= a.z*q.z; S4.w -= a.w*q.w;
            }
        }
    }
}

// ---------------------------------------------------------------------------
// K2: D-filter (float4 register rolling window on transposed fp16 H-sums;
// add streams 320B-stride, subtract reloads are L2-resident even at
// DSPLIT=8 thanks to the halved footprint), then W 9-tap via double-
// buffered float4 smem rows, then cc + global mean.
// Block: 160 threads = 40 quads x 4 h-rows. Grid: 768 (~40% occ).
// ---------------------------------------------------------------------------
__global__ void __launch_bounds__(160)
pass_d_w_cc(const __half* __restrict__ in, float* __restrict__ outscalar) {
    __shared__ float4 sbuf[2][NROWS][NCH][SROW];

    const int blk   = blockIdx.x;
    const int chunk = blk % DSPLIT;
    const int id    = blk / DSPLIT;
    const int hg    = id % (Hn/NROWS);
    const int b     = id / (Hn/NROWS);

    const int tid  = threadIdx.x;
    const int wq   = tid % NQ;
    const int row4 = tid / NQ;                 // 0..3
    const int h    = hg * NROWS + row4;

    // transposed: plane d of row h lives at ((h*Dn + d)*Wn)
    const __half* __restrict__ p =
        in + (size_t)b * DHW + (size_t)h * (Dn * Wn) + 4*wq;

    const int o0 = chunk * DCHUNK;
    const int o1 = o0 + DCHUNK;

    // zero the W pads once (both buffers): 2*4*5*2 = 80 float4s
    for (int i = tid; i < 80; i += 160) {
        const int side = i & 1;
        const int ch   = (i >> 1) % NCH;
        const int rr   = ((i >> 1) / NCH) % NROWS;
        const int bf   = (i >> 1) / (NCH * NROWS);
        sbuf[bf][rr][ch][side ? (SROW-1) : 0] = f4zero();
    }

    // init D window: planes [max(0,o0-4) .. o0+4]
    float4 S0=f4zero(), S1=f4zero(), S2=f4zero(), S3=f4zero(), S4=f4zero();
#pragma unroll
    for (int d = o0 - Rr; d <= o0 + Rr; ++d) {
        if (d >= 0) {
            const size_t off = (size_t)d * Wn;
            float4 v;
            v = ldh4(p + 0*(size_t)NB + off); ADD4(S0,v);
            v = ldh4(p + 1*(size_t)NB + off); ADD4(S1,v);
            v = ldh4(p + 2*(size_t)NB + off); ADD4(S2,v);
            v = ldh4(p + 3*(size_t)NB + off); ADD4(S3,v);
            v = ldh4(p + 4*(size_t)NB + off); ADD4(S4,v);
        }
    }

    const float inv = 1.0f / 729.0f;
    float accf = 0.f;

    for (int o = o0; o < o1; ++o) {
        const int buf = o & 1;
        sbuf[buf][row4][0][1+wq] = S0;
        sbuf[buf][row4][1][1+wq] = S1;
        sbuf[buf][row4][2][1+wq] = S2;
        sbuf[buf][row4][3][1+wq] = S3;
        sbuf[buf][row4][4][1+wq] = S4;
        __syncthreads();

        // W 9-tap from smem (pads give zero boundary), then cc
        float4 W[NCH];
#pragma unroll
        for (int ch = 0; ch < NCH; ++ch) {
            const float4 L = sbuf[buf][row4][ch][wq];
            const float4 C = sbuf[buf][row4][ch][1+wq];
            const float4 R = sbuf[buf][row4][ch][2+wq];
            const float v[12] = {L.x,L.y,L.z,L.w, C.x,C.y,C.z,C.w, R.x,R.y,R.z,R.w};
            W[ch] = slide9(v);
        }
        {
            const float mu1=W[0].x*inv, mu2=W[1].x*inv;
            const float v1=W[2].x*inv-mu1*mu1, v2=W[3].x*inv-mu2*mu2, cv=W[4].x*inv-mu1*mu2;
            accf += __fdividef(cv*cv, v1*v2 + 1e-5f);
        }
        {
            const float mu1=W[0].y*inv, mu2=W[1].y*inv;
            const float v1=W[2].y*inv-mu1*mu1, v2=W[3].y*inv-mu2*mu2, cv=W[4].y*inv-mu1*mu2;
            accf += __fdividef(cv*cv, v1*v2 + 1e-5f);
        }
        {
            const float mu1=W[0].z*inv, mu2=W[1].z*inv;
            const float v1=W[2].z*inv-mu1*mu1, v2=W[3].z*inv-mu2*mu2, cv=W[4].z*inv-mu1*mu2;
            accf += __fdividef(cv*cv, v1*v2 + 1e-5f);
        }
        {
            const float mu1=W[0].w*inv, mu2=W[1].w*inv;
            const float v1=W[2].w*inv-mu1*mu1, v2=W[3].w*inv-mu2*mu2, cv=W[4].w*inv-mu1*mu2;
            accf += __fdividef(cv*cv, v1*v2 + 1e-5f);
        }

        // advance D window (add: streaming; sub: L2-resident reload of the
        // SAME fp16 values -> telescoping in fp32 is exact to fp32 rounding)
        const int da = o + Rr + 1;
        const int ds = o - Rr;
        if (da < Dn) {
            const size_t off = (size_t)da * Wn;
            float4 v;
            v = ldh4(p + 0*(size_t)NB + off); ADD4(S0,v);
            v = ldh4(p + 1*(size_t)NB + off); ADD4(S1,v);
            v = ldh4(p + 2*(size_t)NB + off); ADD4(S2,v);
            v = ldh4(p + 3*(size_t)NB + off); ADD4(S3,v);
            v = ldh4(p + 4*(size_t)NB + off); ADD4(S4,v);
        }
        if (ds >= 0) {
            const size_t off = (size_t)ds * Wn;
            float4 v;
            v = ldh4(p + 0*(size_t)NB + off); SUB4(S0,v);
            v = ldh4(p + 1*(size_t)NB + off); SUB4(S1,v);
            v = ldh4(p + 2*(size_t)NB + off); SUB4(S2,v);
            v = ldh4(p + 3*(size_t)NB + off); SUB4(S3,v);
            v = ldh4(p + 4*(size_t)NB + off); SUB4(S4,v);
        }
        // double-buffered: one sync per plane suffices
    }

    // Deterministic block reduction (160 -> 1)
    __shared__ double red[160];
    const int w = tid;
    red[w] = (double)accf;
    __syncthreads();
    if (w < 32) red[w] += red[w + 128];
    __syncthreads();
#pragma unroll
    for (int s = 64; s > 0; s >>= 1) {
        if (w < s) red[w] += red[w + s];
        __syncthreads();
    }

    __shared__ int isLast;
    if (w == 0) {
        g_part[blk] = red[0];
        __threadfence();
        const unsigned v = atomicAdd(&g_done, 1u);
        isLast = (v == (unsigned)(gridDim.x - 1));
    }
    __syncthreads();

    if (isLast) {
        __threadfence();
        double a = 0.0;
        for (int i = w; i < NPART; i += 160) a += g_part[i];  // fixed order
        red[w] = a;
        __syncthreads();
        if (w < 32) red[w] += red[w + 128];
        __syncthreads();
#pragma unroll
        for (int s = 64; s > 0; s >>= 1) {
            if (w < s) red[w] += red[w + s];
            __syncthreads();
        }
        if (w == 0) {
            outscalar[0] = (float)(-red[0] / (double)NB);
            g_done = 0;   // reset for next graph replay
        }
    }
}

extern "C" void kernel_launch(void* const* d_in, const int* in_sizes, int n_in,
                              void* d_out, int out_size) {
    const float* I = (const float*)d_in[0];   // y_true
    const float* J = (const float*)d_in[1];   // y_pred
    float* out = (float*)d_out;

    void* bufraw;
    cudaGetSymbolAddress(&bufraw, g_buf);
    __half* buf = (__half*)bufraw;

    pass_h<<<Bn * Dn * HSPLIT, 160>>>(I, J, buf);
    pass_d_w_cc<<<Bn * (Hn/NROWS) * DSPLIT, 160>>>(buf, out);
}